// round 10
// baseline (speedup 1.0000x reference)
#include <cuda_runtime.h>

// QLSTM: T=512 steps, B=1024 independent sequences, INPUT_DIM=64, HIDDEN=8.
// One warp per batch element; lane = gate*8 + col (gates: 0=f,1=i,2=u,3=o).
// h, c replicated across the 4 gate-subgroups (each lane holds h_{lane&7}).

#define FULLMASK 0xffffffffu

static constexpr int T_STEPS = 512;
static constexpr int BSZ     = 1024;
static constexpr int IN_DIM  = 64;
static constexpr int HID     = 8;
static constexpr int WARPS_PER_BLOCK = 4;
static constexpr int THREADS = WARPS_PER_BLOCK * 32;
static constexpr int NBLOCKS = BSZ / WARPS_PER_BLOCK;

typedef unsigned long long ull;

__device__ __forceinline__ ull pack2(float lo, float hi) {
    ull r;
    asm("mov.b64 %0, {%1, %2};" : "=l"(r) : "f"(lo), "f"(hi));
    return r;
}
__device__ __forceinline__ void unpack2(ull v, float& lo, float& hi) {
    asm("mov.b64 {%0, %1}, %2;" : "=f"(lo), "=f"(hi) : "l"(v));
}
// Packed f32x2 FMA (Blackwell): d = a*b + c on both halves.
__device__ __forceinline__ ull ffma2(ull a, ull b, ull c) {
    ull d;
    asm("fma.rn.f32x2 %0, %1, %2, %3;" : "=l"(d) : "l"(a), "l"(b), "l"(c));
    return d;
}

__global__ void __launch_bounds__(THREADS)
qlstm_kernel(const float* __restrict__ x,     // [T, B, 64]
             const float* __restrict__ Wf, const float* __restrict__ bf,
             const float* __restrict__ Wi, const float* __restrict__ bi,
             const float* __restrict__ Wu, const float* __restrict__ bu,
             const float* __restrict__ Wo, const float* __restrict__ bo,
             const float* __restrict__ th_f, const float* __restrict__ th_i,
             const float* __restrict__ th_u, const float* __restrict__ th_o,
             const float* __restrict__ Wh2k, const float* __restrict__ bh2k,
             const float* __restrict__ Wi2k, const float* __restrict__ bi2k,
             float* __restrict__ out)         // [T*B*8] outputs ++ [B*8] hx ++ [B*8] cx
{
    const int lane = threadIdx.x & 31;
    const int w    = threadIdx.x >> 5;
    const int b    = blockIdx.x * WARPS_PER_BLOCK + w;   // batch element
    const int g    = lane >> 3;                          // gate index
    const int j    = lane & 7;                           // hidden column
    const int base = lane & 24;                          // subgroup base lane

    // ---- select per-gate parameter pointers ----
    const float* Wg  = (g == 0) ? Wf : (g == 1) ? Wi : (g == 2) ? Wu : Wo;
    const float* bg  = (g == 0) ? bf : (g == 1) ? bi : (g == 2) ? bu : bo;
    const float* thg = (g == 0) ? th_f : (g == 1) ? th_i : (g == 2) ? th_u : th_o;

    // ---- load this lane's weight column into registers ----
    ull wx2[32];                      // x-part of gate column, packed pairs
    #pragma unroll
    for (int m = 0; m < 32; m++)
        wx2[m] = pack2(Wg[(2 * m) * HID + j], Wg[(2 * m + 1) * HID + j]);

    float wh[8], whk[8];
    #pragma unroll
    for (int k = 0; k < 8; k++) {
        wh[k]  = Wg[(IN_DIM + k) * HID + j];
        whk[k] = Wh2k[k * HID + j];
    }

    ull wik2[8];                      // this lane's 16-wide slice of Wi2k column j
    #pragma unroll
    for (int m = 0; m < 8; m++)
        wik2[m] = pack2(Wi2k[(16 * g + 2 * m) * HID + j],
                        Wi2k[(16 * g + 2 * m + 1) * HID + j]);

    const float cth = bg[j] + thg[j];   // bias + RX theta folded
    const float bkx = bh2k[j];
    const float bky = bi2k[j];
    const float scl  = (g == 2) ? 2.0f : 1.0f;    // tanh = 2*sigmoid(2a)-1
    const float addc = (g == 2) ? -1.0f : 0.0f;

    // ---- shared-memory x staging, double buffered per warp ----
    __shared__ __align__(16) float sx[WARPS_PER_BLOCK][2][IN_DIM];

    const float* xb = x + (size_t)b * IN_DIM;
    const size_t tstride = (size_t)BSZ * IN_DIM;

    // preload t=0
    {
        float2 v = *(const float2*)(xb + 2 * lane);
        *(float2*)&sx[w][0][2 * lane] = v;
    }
    __syncwarp();

    float h = 0.0f, c = 0.0f;

    #pragma unroll 1
    for (int t = 0; t < T_STEPS; ++t) {
        const int cur = t & 1, nxt = cur ^ 1;
        const int tn = (t + 1 < T_STEPS) ? (t + 1) : t;
        // prefetch next timestep's x (off critical path)
        float2 nx = *(const float2*)(xb + (size_t)tn * tstride + 2 * lane);

        const float* sxp = sx[w][cur];

        // gate pre-activation: x-part (64 MACs as 32 packed FMA2, 2 accumulators)
        ull acc2a = 0ull, acc2b = 0ull;
        #pragma unroll
        for (int m = 0; m < 32; m += 2) {
            ull xv0 = *(const ull*)(sxp + 2 * m);
            ull xv1 = *(const ull*)(sxp + 2 * m + 2);
            acc2a = ffma2(xv0, wx2[m], acc2a);
            acc2b = ffma2(xv1, wx2[m + 1], acc2b);
        }
        // ky partial: 16 MACs over this lane's x slice
        ull kyacc = 0ull;
        const float* sxg = sxp + 16 * g;
        #pragma unroll
        for (int m = 0; m < 8; m++) {
            ull xv = *(const ull*)(sxg + 2 * m);
            kyacc = ffma2(xv, wik2[m], kyacc);
        }

        float a0, a1, b0, b1;
        unpack2(acc2a, a0, a1);
        unpack2(acc2b, b0, b1);
        float acc = cth + ((a0 + a1) + (b0 + b1));

        float k0, k1;
        unpack2(kyacc, k0, k1);
        float kyp = k0 + k1;
        kyp += __shfl_xor_sync(FULLMASK, kyp, 8);
        kyp += __shfl_xor_sync(FULLMASK, kyp, 16);
        const float ky = kyp + bky;

        // h-dependent parts (critical path starts here)
        float kx = bkx;
        #pragma unroll
        for (int k = 0; k < 8; k++) {
            float hk = __shfl_sync(FULLMASK, h, k);   // h replicated; lane k holds h_k
            acc += hk * wh[k];
            kx  += hk * whk[k];
        }

        const float z  = __cosf(acc);
        const float cw = __cosf(0.5f * (kx - ky));

        // qlayer: gather the 8 z's of this gate subgroup, masked prefix product
        float zv[8];
        #pragma unroll
        for (int i = 0; i < 8; i++)
            zv[i] = __shfl_sync(FULLMASK, z, base + i);
        float m0 = (j == 0) ? 1.0f : zv[0];
        float m2 = (j == 0 || j >= 2) ? zv[2] : 1.0f;
        float m3 = (j == 0 || j >= 3) ? zv[3] : 1.0f;
        float m4 = (j == 0 || j >= 4) ? zv[4] : 1.0f;
        float m5 = (j == 0 || j >= 5) ? zv[5] : 1.0f;
        float m6 = (j == 0 || j >= 6) ? zv[6] : 1.0f;
        float m7 = (j == 7 || j == 0) ? zv[7] : 1.0f;
        float q = ((m0 * zv[1]) * (m2 * m3)) * ((m4 * m5) * (m6 * m7));

        // quantum kernel weight w = |prod_j cos(0.5(kx_j - ky_j))|
        float cv[8];
        #pragma unroll
        for (int i = 0; i < 8; i++)
            cv[i] = __shfl_sync(FULLMASK, cw, base + i);
        float wk = fabsf(((cv[0] * cv[1]) * (cv[2] * cv[3])) *
                         ((cv[4] * cv[5]) * (cv[6] * cv[7])));

        const float a = q * wk;

        // activation: sigmoid for f,i,o; tanh (=2*sigmoid(2a)-1) for u — branchless
        float e = __expf(-scl * a);
        float s = __fdividef(1.0f, 1.0f + e);
        float gate = s * scl + addc;

        // gather f,i,u,o for this hidden column
        float fv = __shfl_sync(FULLMASK, gate, j);
        float iv = __shfl_sync(FULLMASK, gate, 8 + j);
        float uv = __shfl_sync(FULLMASK, gate, 16 + j);
        float ov = __shfl_sync(FULLMASK, gate, 24 + j);

        c = fv * c + iv * uv;
        float e2 = __expf(-2.0f * c);
        float tc = __fdividef(2.0f, 1.0f + e2) - 1.0f;   // tanh(c)
        h = ov * tc;

        if (lane < 8)
            out[((size_t)t * BSZ + b) * HID + lane] = h;

        // stage next x
        *(float2*)&sx[w][nxt][2 * lane] = nx;
        __syncwarp();
    }

    if (lane < 8) {
        const size_t offh = (size_t)T_STEPS * BSZ * HID;
        out[offh + (size_t)b * HID + lane] = h;                          // hx
        out[offh + (size_t)BSZ * HID + (size_t)b * HID + lane] = c;      // cx
    }
}

extern "C" void kernel_launch(void* const* d_in, const int* in_sizes, int n_in,
                              void* d_out, int out_size)
{
    (void)in_sizes; (void)n_in; (void)out_size;
    // Input order follows setup_inputs() dict insertion order:
    // inputs, Wf, bf, th_f, Wi, bi, th_i, Wu, bu, th_u, Wo, bo, th_o,
    // Wh2k, bh2k, Wi2k, bi2k
    const float* x    = (const float*)d_in[0];
    const float* Wf   = (const float*)d_in[1];
    const float* bf   = (const float*)d_in[2];
    const float* th_f = (const float*)d_in[3];
    const float* Wi   = (const float*)d_in[4];
    const float* bi   = (const float*)d_in[5];
    const float* th_i = (const float*)d_in[6];
    const float* Wu   = (const float*)d_in[7];
    const float* bu   = (const float*)d_in[8];
    const float* th_u = (const float*)d_in[9];
    const float* Wo   = (const float*)d_in[10];
    const float* bo   = (const float*)d_in[11];
    const float* th_o = (const float*)d_in[12];
    const float* Wh2k = (const float*)d_in[13];
    const float* bh2k = (const float*)d_in[14];
    const float* Wi2k = (const float*)d_in[15];
    const float* bi2k = (const float*)d_in[16];

    qlstm_kernel<<<NBLOCKS, THREADS>>>(x, Wf, bf, Wi, bi, Wu, bu, Wo, bo,
                                       th_f, th_i, th_u, th_o,
                                       Wh2k, bh2k, Wi2k, bi2k,
                                       (float*)d_out);
}